// round 12
// baseline (speedup 1.0000x reference)
#include <cuda_runtime.h>
#include <cuda_fp16.h>
#include <math.h>

#define B    8
#define NPTS 2048
#define BN   (B * NPTS)
#define CMAT ((size_t)B * NPTS * NPTS)

#define CMAX  1.5707964f
#define QSCL  (65535.0f / CMAX)
#define DQ    (1.5707964 / 65535.0)
#define LOG2E 1.4426950408889634
#define LN2   0.6931471805599453

// ---------------- scratch (allocation-free: __device__ globals) ----------------
__device__ unsigned short d_C[4][B * NPTS * NPTS];   // Cxx, Cyy, Cxy, Cyx
__device__ float d_pot[2][4][BN];
__device__ float d_fin[4][BN];
__device__ float d_g[2][4][BN];                      // double-buffered weights
__device__ float d_la[BN];                           // log2e * log(alpha)
__device__ float d_lb[BN];

// ---------------- helpers ----------------
__device__ __forceinline__ unsigned int qcost(float t) {
    t = fminf(fmaxf(t, -1.0f + 1e-6f), 1.0f - 1e-6f);
    float ax = fabsf(t);
    float u  = 1.0f - ax;                 // >= 1e-6 by the clip
    float s  = u * __frsqrt_rn(u);        // sqrt(u), 1 MUFU + 1 mul
    float p  = -0.0012624911f;
    p = fmaf(p, ax, 0.0066700901f);
    p = fmaf(p, ax, -0.0170881256f);
    p = fmaf(p, ax, 0.0308918810f);
    p = fmaf(p, ax, -0.0501743046f);
    p = fmaf(p, ax, 0.0889789874f);
    p = fmaf(p, ax, -0.2145988016f);
    p = fmaf(p, ax, 1.5707963050f);
    float r = s * p;
    float c = (t < 0.0f) ? (3.14159265359f - r) : r;
    return __float2uint_rn(c * 0.5f * QSCL);
}

// ---------------- kernels ----------------
__global__ void logw_kernel(const float* __restrict__ a, const float* __restrict__ bt,
                            float* __restrict__ la, float* __restrict__ lb) {
    int i = blockIdx.x * blockDim.x + threadIdx.x;
    if (i < BN) {
        float av = a[i];
        la[i] = (float)LOG2E * ((av > 0.f) ? logf(fmaxf(av, 1e-30f)) : -1e5f);
        float bv = bt[i];
        lb[i] = (float)LOG2E * ((bv > 0.f) ? logf(fmaxf(bv, 1e-30f)) : -1e5f);
    }
}

// All three cost jobs in one launch: z = job*8 + batch.
__global__ void cost_all(const float* __restrict__ x, const float* __restrict__ y,
                         unsigned short* __restrict__ Cxx, unsigned short* __restrict__ Cyy,
                         unsigned short* __restrict__ Cxy, unsigned short* __restrict__ Cyx) {
    int job = blockIdx.z >> 3;
    int b   = blockIdx.z & 7;
    const float *P, *Q;
    unsigned short *Co, *Ct;
    int tri;
    if (job == 0)      { P = x; Q = x; Co = Cxx; Ct = Cxx; tri = 1; }
    else if (job == 1) { P = y; Q = y; Co = Cyy; Ct = Cyy; tri = 1; }
    else               { P = x; Q = y; Co = Cxy; Ct = Cyx; tri = 0; }
    if (tri && (int)blockIdx.x < (int)blockIdx.y) return;

    __shared__ float xs[32][3], ys[32][3];
    __shared__ unsigned short t[32][33];
    int n0 = blockIdx.y * 32, m0 = blockIdx.x * 32;
    int tx = threadIdx.x, ty = threadIdx.y;
    int lt = ty * 32 + tx;
    if (lt < 96) {
        xs[lt / 3][lt % 3] = P[((size_t)b * NPTS + n0) * 3 + lt];
        ys[lt / 3][lt % 3] = Q[((size_t)b * NPTS + m0) * 3 + lt];
    }
    __syncthreads();
#pragma unroll
    for (int k = 0; k < 4; k++) {
        int nl = ty + 8 * k;
        float dot = xs[nl][0] * ys[tx][0] + xs[nl][1] * ys[tx][1] + xs[nl][2] * ys[tx][2];
        unsigned int q = qcost(dot);
        t[nl][tx] = (unsigned short)q;
        Co[((size_t)b * NPTS + n0 + nl) * NPTS + m0 + tx] = (unsigned short)q;
    }
    __syncthreads();
#pragma unroll
    for (int k = 0; k < 4; k++) {
        int ml = ty + 8 * k;
        Ct[((size_t)b * NPTS + m0 + ml) * NPTS + n0 + tx] = t[tx][ml];
    }
}

// ---- softmin v5: barrier-free online-softmax, depth-2 prefetch on a
// flattened linear stream. 256 threads = 8 warps; each warp owns 8 CONTIGUOUS
// rows => the sweep is one linear uint4 stream of 64 chunks (32 uint4 each).
// Rotate q0/q1/q2 buffers, always loading chunk c+2: dependent-use distance =
// 2 chunk-computes > DRAM latency. g staged once per block in split even/odd
// float4 smem (conflict-free LDS.128).
struct SmJobs {
    const unsigned short* C[4];
    const float*          gin[4];
    const float*          potold[4];
    float*                out[4];
    float*                gout[4];
    const float*          lw[4];
};

template <bool HEXP>
__global__ void __launch_bounds__(256, 4) softmin_fused(
        SmJobs J, float dqs, float negeln2, float ienl2, int blend) {
    __shared__ float4 sgA[256];      // g elems 8i..8i+3
    __shared__ float4 sgB[256];      // g elems 8i+4..8i+7

    int tid  = threadIdx.x;
    int warp = tid >> 5, lane = tid & 31;
    int job  = blockIdx.y;
    int rbase = blockIdx.x * 64 + warp * 8;    // 8 contiguous rows per warp
    int b     = rbase >> 11;                   // NPTS == 2048

    const uint4* base = (const uint4*)(J.C[job] + (size_t)rbase * NPTS);

    // Issue the first two chunk loads early (independent of staging).
    uint4 q0 = __ldcs(base + lane);
    uint4 q1 = __ldcs(base + 32 + lane);

    // Stage g (512 float4) into split arrays: float4 j even -> sgA[j/2], odd -> sgB[j/2].
    {
        const float4* gp4 = (const float4*)(J.gin[job] + b * NPTS);
        float4 gv0 = gp4[tid];
        float4 gv1 = gp4[tid + 256];
        if (tid & 1) sgB[tid >> 1] = gv0; else sgA[tid >> 1] = gv0;
        int t2 = tid + 256;
        if (t2 & 1) sgB[t2 >> 1] = gv1; else sgA[t2 >> 1] = gv1;
    }
    __syncthreads();

#pragma unroll 1
    for (int k = 0; k < 8; k++) {
        int row = rbase + k;
        float m = 0.f, s = 0.f;
#pragma unroll
        for (int t = 0; t < 8; t++) {
            int c = k * 8 + t;
            // depth-2 prefetch: load chunk c+2 while computing chunk c
            uint4 q2;
            if (c + 2 < 64) q2 = __ldcs(base + (c + 2) * 32 + lane);
            int gi = t * 32 + lane;
            float4 gA = sgA[gi];
            float4 gB = sgB[gi];
            float v0 = fmaf((float)(q0.x & 0xffff), -dqs, gA.x);
            float v1 = fmaf((float)(q0.x >> 16),    -dqs, gA.y);
            float v2 = fmaf((float)(q0.y & 0xffff), -dqs, gA.z);
            float v3 = fmaf((float)(q0.y >> 16),    -dqs, gA.w);
            float v4 = fmaf((float)(q0.z & 0xffff), -dqs, gB.x);
            float v5 = fmaf((float)(q0.z >> 16),    -dqs, gB.y);
            float v6 = fmaf((float)(q0.w & 0xffff), -dqs, gB.z);
            float v7 = fmaf((float)(q0.w >> 16),    -dqs, gB.w);
            float mc = fmaxf(fmaxf(fmaxf(v0, v1), fmaxf(v2, v3)),
                             fmaxf(fmaxf(v4, v5), fmaxf(v6, v7)));
            float sc;
            if (HEXP) {
                __half2 h0 = h2exp2(__floats2half2_rn(v0 - mc, v1 - mc));
                __half2 h1 = h2exp2(__floats2half2_rn(v2 - mc, v3 - mc));
                h0 = __hadd2(h0, h2exp2(__floats2half2_rn(v4 - mc, v5 - mc)));
                h1 = __hadd2(h1, h2exp2(__floats2half2_rn(v6 - mc, v7 - mc)));
                h0 = __hadd2(h0, h1);
                float2 f = __half22float2(h0);
                sc = f.x + f.y;
            } else {
                sc = exp2f(v0 - mc) + exp2f(v1 - mc) + exp2f(v2 - mc) + exp2f(v3 - mc)
                   + exp2f(v4 - mc) + exp2f(v5 - mc) + exp2f(v6 - mc) + exp2f(v7 - mc);
            }
            if (t == 0) {
                m = mc; s = sc;
            } else {
                float M = fmaxf(m, mc);
                s = s * exp2f(m - M) + sc * exp2f(mc - M);
                m = M;
            }
            q0 = q1;
            q1 = q2;
        }
        // warp-level (m,s) merge
#pragma unroll
        for (int o = 16; o; o >>= 1) {
            float mo = __shfl_xor_sync(0xffffffffu, m, o);
            float so = __shfl_xor_sync(0xffffffffu, s, o);
            float M  = fmaxf(m, mo);
            s = s * exp2f(m - M) + so * exp2f(mo - M);
            m = M;
        }
        if (lane == 0) {
            float r = negeln2 * (m + log2f(s));
            if (blend) r = 0.5f * (J.potold[job][row] + r);
            J.out[job][row] = r;
            if (J.gout[job])
                J.gout[job][row] = fmaf(r, ienl2, J.lw[job][row]);
        }
    }
}

__global__ void loss_kernel(const float* __restrict__ alpha, const float* __restrict__ beta,
                            float* __restrict__ out) {
    __shared__ double red[8];
    int b = blockIdx.x, tid = threadIdx.x;
    double acc = 0.0;
    for (int i = tid; i < NPTS; i += 256) {
        int idx = b * NPTS + i;
        acc += (double)alpha[idx] * ((double)d_fin[3][idx] - (double)d_fin[0][idx]);
        acc += (double)beta[idx]  * ((double)d_fin[2][idx] - (double)d_fin[1][idx]);
    }
#pragma unroll
    for (int o = 16; o; o >>= 1)
        acc += __shfl_xor_sync(0xffffffffu, acc, o);
    if ((tid & 31) == 0) red[tid >> 5] = acc;
    __syncthreads();
    if (tid == 0) {
        double tot = red[0];
#pragma unroll
        for (int i = 1; i < 8; i++) tot += red[i];
        out[b] = (float)tot;
    }
}

// ---------------- host orchestration ----------------
extern "C" void kernel_launch(void* const* d_in, const int* in_sizes, int n_in,
                              void* d_out, int out_size) {
    const float* alpha = (const float*)d_in[0];
    const float* x     = (const float*)d_in[1];
    const float* beta  = (const float*)d_in[2];
    const float* y     = (const float*)d_in[3];
    float* out = (float*)d_out;

    unsigned short* C_;
    float *pot_, *fin_, *g_, *la_, *lb_;
    cudaGetSymbolAddress((void**)&C_,   d_C);
    cudaGetSymbolAddress((void**)&pot_, d_pot);
    cudaGetSymbolAddress((void**)&fin_, d_fin);
    cudaGetSymbolAddress((void**)&g_,   d_g);
    cudaGetSymbolAddress((void**)&la_,  d_la);
    cudaGetSymbolAddress((void**)&lb_,  d_lb);

    unsigned short* Cxx = C_ + 0 * CMAT;
    unsigned short* Cyy = C_ + 1 * CMAT;
    unsigned short* Cxy = C_ + 2 * CMAT;
    unsigned short* Cyx = C_ + 3 * CMAT;
    auto POT = [&](int buf, int j) { return pot_ + ((size_t)buf * 4 + j) * BN; };
    auto G   = [&](int bank, int j) { return g_ + ((size_t)bank * 4 + j) * BN; };

    logw_kernel<<<(BN + 255) / 256, 256>>>(alpha, beta, la_, lb_);

    cost_all<<<dim3(NPTS / 32, NPTS / 32, 24), dim3(32, 8)>>>(x, y, Cxx, Cyy, Cxy, Cyx);

    const double eps_list[8] = {
        4.0, 3.9999999999999996, 1.0, 0.25, 0.0625, 0.015625, 0.00390625, 0.0025
    };

    const unsigned short* CJ[4] = {Cxx, Cyy, Cyx, Cxy};
    const int GOUTI[4] = {0, 1, 3, 2};
    const float* LW[4] = {la_, lb_, lb_, la_};

    const int gx = BN / 64;      // 256 blocks per job
    dim3 smg(gx, 4);

    // ---- init (eps = 4) ----
    {
        double eps = 4.0, eps_next = eps_list[0];
        SmJobs J;
        for (int j = 0; j < 4; j++) {
            J.C[j] = CJ[j];
            J.gin[j] = (j == 0 || j == 2) ? la_ : lb_;
            J.potold[j] = nullptr;
            J.out[j] = POT(0, j);
            J.gout[j] = G(0, GOUTI[j]);
            J.lw[j] = LW[j];
        }
        softmin_fused<true><<<smg, 256>>>(J, (float)(DQ * LOG2E / eps),
                                          (float)(-eps * LN2),
                                          (float)(LOG2E / eps_next), 0);
    }

    // ---- annealed loop ----
    int cur = 0, gb = 0;
    for (int i = 0; i < 8; i++) {
        double eps = eps_list[i];
        double eps_next = (i < 7) ? eps_list[i + 1] : 0.0025;
        int nxt = cur ^ 1;
        SmJobs J;
        for (int j = 0; j < 4; j++) {
            J.C[j] = CJ[j];
            J.gin[j] = G(gb, j);
            J.potold[j] = POT(cur, j);
            J.out[j] = POT(nxt, j);
            J.gout[j] = G(gb ^ 1, GOUTI[j]);
            J.lw[j] = LW[j];
        }
        softmin_fused<true><<<smg, 256>>>(J, (float)(DQ * LOG2E / eps),
                                          (float)(-eps * LN2),
                                          (float)(LOG2E / eps_next), 1);
        cur = nxt;
        gb ^= 1;
    }

    // ---- final extrapolation (fp32 exp path), SEQUENTIAL: b_x uses fresh a_y ----
    {
        double eps = 0.0025;
        float dqs = (float)(DQ * LOG2E / eps);
        float nel = (float)(-eps * LN2);
        float ien = (float)(LOG2E / eps);
        SmJobs J;
        for (int j = 0; j < 3; j++) {
            J.C[j] = CJ[j];
            J.gin[j] = G(gb, j);
            J.potold[j] = nullptr;
            J.out[j] = fin_ + (size_t)j * BN;
            J.gout[j] = (j == 2) ? G(gb ^ 1, 3) : nullptr;
            J.lw[j] = LW[j];
        }
        J.C[3] = CJ[3]; J.gin[3] = G(gb, 3); J.potold[3] = nullptr;
        J.out[3] = fin_ + 3 * (size_t)BN; J.gout[3] = nullptr; J.lw[3] = LW[3];
        softmin_fused<false><<<dim3(gx, 3), 256>>>(J, dqs, nel, ien, 0);

        SmJobs J2;
        for (int j = 0; j < 4; j++) {
            J2.C[j] = Cxy; J2.gin[j] = G(gb ^ 1, 3); J2.potold[j] = nullptr;
            J2.out[j] = fin_ + 3 * (size_t)BN; J2.gout[j] = nullptr; J2.lw[j] = lb_;
        }
        softmin_fused<false><<<dim3(gx, 1), 256>>>(J2, dqs, nel, ien, 0);
    }

    loss_kernel<<<B, 256>>>(alpha, beta, out);
}

// round 13
// speedup vs baseline: 1.1640x; 1.1640x over previous
#include <cuda_runtime.h>
#include <cuda_fp16.h>
#include <math.h>

#define B    8
#define NPTS 2048
#define BN   (B * NPTS)
#define CMAT ((size_t)B * NPTS * NPTS)

#define CMAX  1.5707964f
#define QSCL  (65535.0f / CMAX)
#define DQ    (1.5707964 / 65535.0)
#define LOG2E 1.4426950408889634
#define LN2   0.6931471805599453

// ---------------- scratch (allocation-free: __device__ globals) ----------------
__device__ unsigned short d_C[4][B * NPTS * NPTS];   // Cxx, Cyy, Cxy, Cyx
__device__ float d_pot[2][4][BN];
__device__ float d_fin[4][BN];
__device__ float d_g[2][4][BN];                      // double-buffered weights
__device__ float d_la[BN];                           // log2e * log(alpha)
__device__ float d_lb[BN];

// ---------------- helpers ----------------
__device__ __forceinline__ unsigned int qcost(float t) {
    t = fminf(fmaxf(t, -1.0f + 1e-6f), 1.0f - 1e-6f);
    float ax = fabsf(t);
    float u  = 1.0f - ax;                 // >= 1e-6 by the clip
    float s  = u * __frsqrt_rn(u);        // sqrt(u), 1 MUFU + 1 mul
    float p  = -0.0012624911f;
    p = fmaf(p, ax, 0.0066700901f);
    p = fmaf(p, ax, -0.0170881256f);
    p = fmaf(p, ax, 0.0308918810f);
    p = fmaf(p, ax, -0.0501743046f);
    p = fmaf(p, ax, 0.0889789874f);
    p = fmaf(p, ax, -0.2145988016f);
    p = fmaf(p, ax, 1.5707963050f);
    float r = s * p;
    float c = (t < 0.0f) ? (3.14159265359f - r) : r;
    return __float2uint_rn(c * 0.5f * QSCL);
}

// ---------------- kernels ----------------
__global__ void logw_kernel(const float* __restrict__ a, const float* __restrict__ bt,
                            float* __restrict__ la, float* __restrict__ lb) {
    int i = blockIdx.x * blockDim.x + threadIdx.x;
    if (i < BN) {
        float av = a[i];
        la[i] = (float)LOG2E * ((av > 0.f) ? logf(fmaxf(av, 1e-30f)) : -1e5f);
        float bv = bt[i];
        lb[i] = (float)LOG2E * ((bv > 0.f) ? logf(fmaxf(bv, 1e-30f)) : -1e5f);
    }
}

// All three cost jobs in one launch: z = job*8 + batch.
__global__ void cost_all(const float* __restrict__ x, const float* __restrict__ y,
                         unsigned short* __restrict__ Cxx, unsigned short* __restrict__ Cyy,
                         unsigned short* __restrict__ Cxy, unsigned short* __restrict__ Cyx) {
    int job = blockIdx.z >> 3;
    int b   = blockIdx.z & 7;
    const float *P, *Q;
    unsigned short *Co, *Ct;
    int tri;
    if (job == 0)      { P = x; Q = x; Co = Cxx; Ct = Cxx; tri = 1; }
    else if (job == 1) { P = y; Q = y; Co = Cyy; Ct = Cyy; tri = 1; }
    else               { P = x; Q = y; Co = Cxy; Ct = Cyx; tri = 0; }
    if (tri && (int)blockIdx.x < (int)blockIdx.y) return;

    __shared__ float xs[32][3], ys[32][3];
    __shared__ unsigned short t[32][33];
    int n0 = blockIdx.y * 32, m0 = blockIdx.x * 32;
    int tx = threadIdx.x, ty = threadIdx.y;
    int lt = ty * 32 + tx;
    if (lt < 96) {
        xs[lt / 3][lt % 3] = P[((size_t)b * NPTS + n0) * 3 + lt];
        ys[lt / 3][lt % 3] = Q[((size_t)b * NPTS + m0) * 3 + lt];
    }
    __syncthreads();
#pragma unroll
    for (int k = 0; k < 4; k++) {
        int nl = ty + 8 * k;
        float dot = xs[nl][0] * ys[tx][0] + xs[nl][1] * ys[tx][1] + xs[nl][2] * ys[tx][2];
        unsigned int q = qcost(dot);
        t[nl][tx] = (unsigned short)q;
        Co[((size_t)b * NPTS + n0 + nl) * NPTS + m0 + tx] = (unsigned short)q;
    }
    __syncthreads();
#pragma unroll
    for (int k = 0; k < 4; k++) {
        int ml = ty + 8 * k;
        Ct[((size_t)b * NPTS + m0 + ml) * NPTS + n0 + tx] = t[tx][ml];
    }
}

// ---- softmin v6 = v4 (R11) + forced 5 blocks/SM.
// Barrier-free online-softmax streaming: 256 threads = 8 warps; each warp owns
// 8 contiguous rows, depth-1 register prefetch crossing row boundaries.
// g staged once per block in split even/odd float4 smem (conflict-free LDS.128).
struct SmJobs {
    const unsigned short* C[4];
    const float*          gin[4];
    const float*          potold[4];
    float*                out[4];
    float*                gout[4];
    const float*          lw[4];
};

template <bool HEXP>
__global__ void __launch_bounds__(256, 5) softmin_fused(
        SmJobs J, float dqs, float negeln2, float ienl2, int blend) {
    __shared__ float4 sgA[256];      // g elems 8i..8i+3
    __shared__ float4 sgB[256];      // g elems 8i+4..8i+7

    int tid  = threadIdx.x;
    int warp = tid >> 5, lane = tid & 31;
    int job  = blockIdx.y;
    int rbase = blockIdx.x * 64 + warp * 8;    // 8 contiguous rows per warp
    int b     = rbase >> 11;                   // NPTS == 2048

    const unsigned short* Cb = J.C[job];

    // Issue first chunk load early (independent of staging).
    const uint4* cp0 = (const uint4*)(Cb + (size_t)rbase * NPTS);
    uint4 q = __ldcs(cp0 + lane);

    // Stage g (512 float4) into split arrays: float4 j even -> sgA[j/2], odd -> sgB[j/2].
    {
        const float4* gp4 = (const float4*)(J.gin[job] + b * NPTS);
        float4 gv0 = gp4[tid];
        float4 gv1 = gp4[tid + 256];
        if (tid & 1) sgB[tid >> 1] = gv0; else sgA[tid >> 1] = gv0;
        int t2 = tid + 256;
        if (t2 & 1) sgB[t2 >> 1] = gv1; else sgA[t2 >> 1] = gv1;
    }
    __syncthreads();

#pragma unroll 1
    for (int k = 0; k < 8; k++) {
        int row = rbase + k;
        float m = 0.f, s = 0.f;
#pragma unroll
        for (int t = 0; t < 8; t++) {
            // prefetch next chunk: next chunk of this row, or chunk 0 of next row
            uint4 qn;
            if (t < 7) {
                qn = __ldcs((const uint4*)(Cb + (size_t)row * NPTS) + (t + 1) * 32 + lane);
            } else if (k < 7) {
                qn = __ldcs((const uint4*)(Cb + (size_t)(row + 1) * NPTS) + lane);
            }
            int gi = t * 32 + lane;
            float4 gA = sgA[gi];
            float4 gB = sgB[gi];
            float v0 = fmaf((float)(q.x & 0xffff), -dqs, gA.x);
            float v1 = fmaf((float)(q.x >> 16),    -dqs, gA.y);
            float v2 = fmaf((float)(q.y & 0xffff), -dqs, gA.z);
            float v3 = fmaf((float)(q.y >> 16),    -dqs, gA.w);
            float v4 = fmaf((float)(q.z & 0xffff), -dqs, gB.x);
            float v5 = fmaf((float)(q.z >> 16),    -dqs, gB.y);
            float v6 = fmaf((float)(q.w & 0xffff), -dqs, gB.z);
            float v7 = fmaf((float)(q.w >> 16),    -dqs, gB.w);
            float mc = fmaxf(fmaxf(fmaxf(v0, v1), fmaxf(v2, v3)),
                             fmaxf(fmaxf(v4, v5), fmaxf(v6, v7)));
            float sc;
            if (HEXP) {
                __half2 h0 = h2exp2(__floats2half2_rn(v0 - mc, v1 - mc));
                __half2 h1 = h2exp2(__floats2half2_rn(v2 - mc, v3 - mc));
                h0 = __hadd2(h0, h2exp2(__floats2half2_rn(v4 - mc, v5 - mc)));
                h1 = __hadd2(h1, h2exp2(__floats2half2_rn(v6 - mc, v7 - mc)));
                h0 = __hadd2(h0, h1);
                float2 f = __half22float2(h0);
                sc = f.x + f.y;
            } else {
                sc = exp2f(v0 - mc) + exp2f(v1 - mc) + exp2f(v2 - mc) + exp2f(v3 - mc)
                   + exp2f(v4 - mc) + exp2f(v5 - mc) + exp2f(v6 - mc) + exp2f(v7 - mc);
            }
            if (t == 0) {
                m = mc; s = sc;
            } else {
                float M = fmaxf(m, mc);
                s = s * exp2f(m - M) + sc * exp2f(mc - M);
                m = M;
            }
            q = qn;
        }
        // warp-level (m,s) merge
#pragma unroll
        for (int o = 16; o; o >>= 1) {
            float mo = __shfl_xor_sync(0xffffffffu, m, o);
            float so = __shfl_xor_sync(0xffffffffu, s, o);
            float M  = fmaxf(m, mo);
            s = s * exp2f(m - M) + so * exp2f(mo - M);
            m = M;
        }
        if (lane == 0) {
            float r = negeln2 * (m + log2f(s));
            if (blend) r = 0.5f * (J.potold[job][row] + r);
            J.out[job][row] = r;
            if (J.gout[job])
                J.gout[job][row] = fmaf(r, ienl2, J.lw[job][row]);
        }
    }
}

__global__ void loss_kernel(const float* __restrict__ alpha, const float* __restrict__ beta,
                            float* __restrict__ out) {
    __shared__ double red[8];
    int b = blockIdx.x, tid = threadIdx.x;
    double acc = 0.0;
    for (int i = tid; i < NPTS; i += 256) {
        int idx = b * NPTS + i;
        acc += (double)alpha[idx] * ((double)d_fin[3][idx] - (double)d_fin[0][idx]);
        acc += (double)beta[idx]  * ((double)d_fin[2][idx] - (double)d_fin[1][idx]);
    }
#pragma unroll
    for (int o = 16; o; o >>= 1)
        acc += __shfl_xor_sync(0xffffffffu, acc, o);
    if ((tid & 31) == 0) red[tid >> 5] = acc;
    __syncthreads();
    if (tid == 0) {
        double tot = red[0];
#pragma unroll
        for (int i = 1; i < 8; i++) tot += red[i];
        out[b] = (float)tot;
    }
}

// ---------------- host orchestration ----------------
extern "C" void kernel_launch(void* const* d_in, const int* in_sizes, int n_in,
                              void* d_out, int out_size) {
    const float* alpha = (const float*)d_in[0];
    const float* x     = (const float*)d_in[1];
    const float* beta  = (const float*)d_in[2];
    const float* y     = (const float*)d_in[3];
    float* out = (float*)d_out;

    unsigned short* C_;
    float *pot_, *fin_, *g_, *la_, *lb_;
    cudaGetSymbolAddress((void**)&C_,   d_C);
    cudaGetSymbolAddress((void**)&pot_, d_pot);
    cudaGetSymbolAddress((void**)&fin_, d_fin);
    cudaGetSymbolAddress((void**)&g_,   d_g);
    cudaGetSymbolAddress((void**)&la_,  d_la);
    cudaGetSymbolAddress((void**)&lb_,  d_lb);

    unsigned short* Cxx = C_ + 0 * CMAT;
    unsigned short* Cyy = C_ + 1 * CMAT;
    unsigned short* Cxy = C_ + 2 * CMAT;
    unsigned short* Cyx = C_ + 3 * CMAT;
    auto POT = [&](int buf, int j) { return pot_ + ((size_t)buf * 4 + j) * BN; };
    auto G   = [&](int bank, int j) { return g_ + ((size_t)bank * 4 + j) * BN; };

    logw_kernel<<<(BN + 255) / 256, 256>>>(alpha, beta, la_, lb_);

    cost_all<<<dim3(NPTS / 32, NPTS / 32, 24), dim3(32, 8)>>>(x, y, Cxx, Cyy, Cxy, Cyx);

    const double eps_list[8] = {
        4.0, 3.9999999999999996, 1.0, 0.25, 0.0625, 0.015625, 0.00390625, 0.0025
    };

    const unsigned short* CJ[4] = {Cxx, Cyy, Cyx, Cxy};
    const int GOUTI[4] = {0, 1, 3, 2};
    const float* LW[4] = {la_, lb_, lb_, la_};

    const int gx = BN / 64;      // 256 blocks per job
    dim3 smg(gx, 4);

    // ---- init (eps = 4) ----
    {
        double eps = 4.0, eps_next = eps_list[0];
        SmJobs J;
        for (int j = 0; j < 4; j++) {
            J.C[j] = CJ[j];
            J.gin[j] = (j == 0 || j == 2) ? la_ : lb_;
            J.potold[j] = nullptr;
            J.out[j] = POT(0, j);
            J.gout[j] = G(0, GOUTI[j]);
            J.lw[j] = LW[j];
        }
        softmin_fused<true><<<smg, 256>>>(J, (float)(DQ * LOG2E / eps),
                                          (float)(-eps * LN2),
                                          (float)(LOG2E / eps_next), 0);
    }

    // ---- annealed loop ----
    int cur = 0, gb = 0;
    for (int i = 0; i < 8; i++) {
        double eps = eps_list[i];
        double eps_next = (i < 7) ? eps_list[i + 1] : 0.0025;
        int nxt = cur ^ 1;
        SmJobs J;
        for (int j = 0; j < 4; j++) {
            J.C[j] = CJ[j];
            J.gin[j] = G(gb, j);
            J.potold[j] = POT(cur, j);
            J.out[j] = POT(nxt, j);
            J.gout[j] = G(gb ^ 1, GOUTI[j]);
            J.lw[j] = LW[j];
        }
        softmin_fused<true><<<smg, 256>>>(J, (float)(DQ * LOG2E / eps),
                                          (float)(-eps * LN2),
                                          (float)(LOG2E / eps_next), 1);
        cur = nxt;
        gb ^= 1;
    }

    // ---- final extrapolation (fp32 exp path), SEQUENTIAL: b_x uses fresh a_y ----
    {
        double eps = 0.0025;
        float dqs = (float)(DQ * LOG2E / eps);
        float nel = (float)(-eps * LN2);
        float ien = (float)(LOG2E / eps);
        SmJobs J;
        for (int j = 0; j < 3; j++) {
            J.C[j] = CJ[j];
            J.gin[j] = G(gb, j);
            J.potold[j] = nullptr;
            J.out[j] = fin_ + (size_t)j * BN;
            J.gout[j] = (j == 2) ? G(gb ^ 1, 3) : nullptr;
            J.lw[j] = LW[j];
        }
        J.C[3] = CJ[3]; J.gin[3] = G(gb, 3); J.potold[3] = nullptr;
        J.out[3] = fin_ + 3 * (size_t)BN; J.gout[3] = nullptr; J.lw[3] = LW[3];
        softmin_fused<false><<<dim3(gx, 3), 256>>>(J, dqs, nel, ien, 0);

        SmJobs J2;
        for (int j = 0; j < 4; j++) {
            J2.C[j] = Cxy; J2.gin[j] = G(gb ^ 1, 3); J2.potold[j] = nullptr;
            J2.out[j] = fin_ + 3 * (size_t)BN; J2.gout[j] = nullptr; J2.lw[j] = lb_;
        }
        softmin_fused<false><<<dim3(gx, 1), 256>>>(J2, dqs, nel, ien, 0);
    }

    loss_kernel<<<B, 256>>>(alpha, beta, out);
}

// round 14
// speedup vs baseline: 1.4247x; 1.2240x over previous
#include <cuda_runtime.h>
#include <cuda_fp16.h>
#include <math.h>

#define B    8
#define NPTS 2048
#define BN   (B * NPTS)
#define CMAT ((size_t)B * NPTS * NPTS)

#define CMAX  1.5707964f
#define QSCL  (65535.0f / CMAX)
#define DQ    (1.5707964 / 65535.0)
#define LOG2E 1.4426950408889634
#define LN2   0.6931471805599453

#define RPW   2            // rows per warp -> 16 rows per 256-thread block

// ---------------- scratch (allocation-free: __device__ globals) ----------------
__device__ unsigned short d_C[4][B * NPTS * NPTS];   // Cxx, Cyy, Cxy, Cyx
__device__ float d_pot[2][4][BN];
__device__ float d_fin[4][BN];
__device__ float d_g[2][4][BN];                      // double-buffered weights
__device__ float d_la[BN];                           // log2e * log(alpha)
__device__ float d_lb[BN];

// ---------------- helpers ----------------
__device__ __forceinline__ unsigned int qcost(float t) {
    t = fminf(fmaxf(t, -1.0f + 1e-6f), 1.0f - 1e-6f);
    float ax = fabsf(t);
    float u  = 1.0f - ax;                 // >= 1e-6 by the clip
    float s  = u * __frsqrt_rn(u);        // sqrt(u), 1 MUFU + 1 mul
    float p  = -0.0012624911f;
    p = fmaf(p, ax, 0.0066700901f);
    p = fmaf(p, ax, -0.0170881256f);
    p = fmaf(p, ax, 0.0308918810f);
    p = fmaf(p, ax, -0.0501743046f);
    p = fmaf(p, ax, 0.0889789874f);
    p = fmaf(p, ax, -0.2145988016f);
    p = fmaf(p, ax, 1.5707963050f);
    float r = s * p;
    float c = (t < 0.0f) ? (3.14159265359f - r) : r;
    return __float2uint_rn(c * 0.5f * QSCL);
}

// ---------------- kernels ----------------
__global__ void logw_kernel(const float* __restrict__ a, const float* __restrict__ bt,
                            float* __restrict__ la, float* __restrict__ lb) {
    int i = blockIdx.x * blockDim.x + threadIdx.x;
    if (i < BN) {
        float av = a[i];
        la[i] = (float)LOG2E * ((av > 0.f) ? logf(fmaxf(av, 1e-30f)) : -1e5f);
        float bv = bt[i];
        lb[i] = (float)LOG2E * ((bv > 0.f) ? logf(fmaxf(bv, 1e-30f)) : -1e5f);
    }
}

// All three cost jobs in one launch: z = job*8 + batch.
__global__ void cost_all(const float* __restrict__ x, const float* __restrict__ y,
                         unsigned short* __restrict__ Cxx, unsigned short* __restrict__ Cyy,
                         unsigned short* __restrict__ Cxy, unsigned short* __restrict__ Cyx) {
    int job = blockIdx.z >> 3;
    int b   = blockIdx.z & 7;
    const float *P, *Q;
    unsigned short *Co, *Ct;
    int tri;
    if (job == 0)      { P = x; Q = x; Co = Cxx; Ct = Cxx; tri = 1; }
    else if (job == 1) { P = y; Q = y; Co = Cyy; Ct = Cyy; tri = 1; }
    else               { P = x; Q = y; Co = Cxy; Ct = Cyx; tri = 0; }
    if (tri && (int)blockIdx.x < (int)blockIdx.y) return;

    __shared__ float xs[32][3], ys[32][3];
    __shared__ unsigned short t[32][33];
    int n0 = blockIdx.y * 32, m0 = blockIdx.x * 32;
    int tx = threadIdx.x, ty = threadIdx.y;
    int lt = ty * 32 + tx;
    if (lt < 96) {
        xs[lt / 3][lt % 3] = P[((size_t)b * NPTS + n0) * 3 + lt];
        ys[lt / 3][lt % 3] = Q[((size_t)b * NPTS + m0) * 3 + lt];
    }
    __syncthreads();
#pragma unroll
    for (int k = 0; k < 4; k++) {
        int nl = ty + 8 * k;
        float dot = xs[nl][0] * ys[tx][0] + xs[nl][1] * ys[tx][1] + xs[nl][2] * ys[tx][2];
        unsigned int q = qcost(dot);
        t[nl][tx] = (unsigned short)q;
        Co[((size_t)b * NPTS + n0 + nl) * NPTS + m0 + tx] = (unsigned short)q;
    }
    __syncthreads();
#pragma unroll
    for (int k = 0; k < 4; k++) {
        int ml = ty + 8 * k;
        Ct[((size_t)b * NPTS + m0 + ml) * NPTS + n0 + tx] = t[tx][ml];
    }
}

// ---- softmin v7: barrier-free online-softmax streaming, PRMT magic unpack,
// 2 rows/warp for wave balance. g' = g + 2^23*dqs staged in split even/odd
// float4 smem; per-element: f = bits(0x4B00'c) = 2^23 + c, v = fma(f,-dqs,g').
struct SmJobs {
    const unsigned short* C[4];
    const float*          gin[4];
    const float*          potold[4];
    float*                out[4];
    float*                gout[4];
    const float*          lw[4];
};

template <bool HEXP>
__global__ void __launch_bounds__(256, 5) softmin_fused(
        SmJobs J, float dqs, float goff, float negeln2, float ienl2, int blend) {
    __shared__ float4 sgA[256];      // g' elems 8i..8i+3
    __shared__ float4 sgB[256];      // g' elems 8i+4..8i+7

    int tid  = threadIdx.x;
    int warp = tid >> 5, lane = tid & 31;
    int job  = blockIdx.y;
    int rbase = blockIdx.x * (8 * RPW) + warp * RPW;   // RPW contiguous rows per warp
    int b     = rbase >> 11;                           // NPTS == 2048

    const unsigned short* Cb = J.C[job];

    // Issue first chunk load early (independent of staging).
    const uint4* cp0 = (const uint4*)(Cb + (size_t)rbase * NPTS);
    uint4 q = __ldcs(cp0 + lane);

    // Stage g' = g + goff (512 float4) into split arrays.
    {
        const float4* gp4 = (const float4*)(J.gin[job] + b * NPTS);
        float4 gv0 = gp4[tid];
        float4 gv1 = gp4[tid + 256];
        gv0.x += goff; gv0.y += goff; gv0.z += goff; gv0.w += goff;
        gv1.x += goff; gv1.y += goff; gv1.z += goff; gv1.w += goff;
        if (tid & 1) sgB[tid >> 1] = gv0; else sgA[tid >> 1] = gv0;
        int t2 = tid + 256;
        if (t2 & 1) sgB[t2 >> 1] = gv1; else sgA[t2 >> 1] = gv1;
    }
    __syncthreads();

#pragma unroll
    for (int k = 0; k < RPW; k++) {
        int row = rbase + k;
        float m = 0.f, s = 0.f;
#pragma unroll
        for (int t = 0; t < 8; t++) {
            // prefetch next chunk: next chunk of this row, or chunk 0 of next row
            uint4 qn;
            if (t < 7) {
                qn = __ldcs((const uint4*)(Cb + (size_t)row * NPTS) + (t + 1) * 32 + lane);
            } else if (k < RPW - 1) {
                qn = __ldcs((const uint4*)(Cb + (size_t)(row + 1) * NPTS) + lane);
            }
            int gi = t * 32 + lane;
            float4 gA = sgA[gi];
            float4 gB = sgB[gi];
            // PRMT magic unpack: f = float bits [c_lo16 | 0x4B000000] = 2^23 + c
            float f0 = __uint_as_float(__byte_perm(q.x, 0x4B000000u, 0x7410));
            float f1 = __uint_as_float(__byte_perm(q.x, 0x4B000000u, 0x7432));
            float f2 = __uint_as_float(__byte_perm(q.y, 0x4B000000u, 0x7410));
            float f3 = __uint_as_float(__byte_perm(q.y, 0x4B000000u, 0x7432));
            float f4 = __uint_as_float(__byte_perm(q.z, 0x4B000000u, 0x7410));
            float f5 = __uint_as_float(__byte_perm(q.z, 0x4B000000u, 0x7432));
            float f6 = __uint_as_float(__byte_perm(q.w, 0x4B000000u, 0x7410));
            float f7 = __uint_as_float(__byte_perm(q.w, 0x4B000000u, 0x7432));
            float v0 = fmaf(f0, -dqs, gA.x);
            float v1 = fmaf(f1, -dqs, gA.y);
            float v2 = fmaf(f2, -dqs, gA.z);
            float v3 = fmaf(f3, -dqs, gA.w);
            float v4 = fmaf(f4, -dqs, gB.x);
            float v5 = fmaf(f5, -dqs, gB.y);
            float v6 = fmaf(f6, -dqs, gB.z);
            float v7 = fmaf(f7, -dqs, gB.w);
            float mc = fmaxf(fmaxf(fmaxf(v0, v1), fmaxf(v2, v3)),
                             fmaxf(fmaxf(v4, v5), fmaxf(v6, v7)));
            float sc;
            if (HEXP) {
                __half2 h0 = h2exp2(__floats2half2_rn(v0 - mc, v1 - mc));
                __half2 h1 = h2exp2(__floats2half2_rn(v2 - mc, v3 - mc));
                h0 = __hadd2(h0, h2exp2(__floats2half2_rn(v4 - mc, v5 - mc)));
                h1 = __hadd2(h1, h2exp2(__floats2half2_rn(v6 - mc, v7 - mc)));
                h0 = __hadd2(h0, h1);
                float2 f = __half22float2(h0);
                sc = f.x + f.y;
            } else {
                sc = exp2f(v0 - mc) + exp2f(v1 - mc) + exp2f(v2 - mc) + exp2f(v3 - mc)
                   + exp2f(v4 - mc) + exp2f(v5 - mc) + exp2f(v6 - mc) + exp2f(v7 - mc);
            }
            if (t == 0) {
                m = mc; s = sc;
            } else {
                float M = fmaxf(m, mc);
                s = s * exp2f(m - M) + sc * exp2f(mc - M);
                m = M;
            }
            q = qn;
        }
        // warp-level (m,s) merge
#pragma unroll
        for (int o = 16; o; o >>= 1) {
            float mo = __shfl_xor_sync(0xffffffffu, m, o);
            float so = __shfl_xor_sync(0xffffffffu, s, o);
            float M  = fmaxf(m, mo);
            s = s * exp2f(m - M) + so * exp2f(mo - M);
            m = M;
        }
        if (lane == 0) {
            float r = negeln2 * (m + log2f(s));
            if (blend) r = 0.5f * (J.potold[job][row] + r);
            J.out[job][row] = r;
            if (J.gout[job])
                J.gout[job][row] = fmaf(r, ienl2, J.lw[job][row]);
        }
    }
}

__global__ void loss_kernel(const float* __restrict__ alpha, const float* __restrict__ beta,
                            float* __restrict__ out) {
    __shared__ double red[8];
    int b = blockIdx.x, tid = threadIdx.x;
    double acc = 0.0;
    for (int i = tid; i < NPTS; i += 256) {
        int idx = b * NPTS + i;
        acc += (double)alpha[idx] * ((double)d_fin[3][idx] - (double)d_fin[0][idx]);
        acc += (double)beta[idx]  * ((double)d_fin[2][idx] - (double)d_fin[1][idx]);
    }
#pragma unroll
    for (int o = 16; o; o >>= 1)
        acc += __shfl_xor_sync(0xffffffffu, acc, o);
    if ((tid & 31) == 0) red[tid >> 5] = acc;
    __syncthreads();
    if (tid == 0) {
        double tot = red[0];
#pragma unroll
        for (int i = 1; i < 8; i++) tot += red[i];
        out[b] = (float)tot;
    }
}

// ---------------- host orchestration ----------------
extern "C" void kernel_launch(void* const* d_in, const int* in_sizes, int n_in,
                              void* d_out, int out_size) {
    const float* alpha = (const float*)d_in[0];
    const float* x     = (const float*)d_in[1];
    const float* beta  = (const float*)d_in[2];
    const float* y     = (const float*)d_in[3];
    float* out = (float*)d_out;

    unsigned short* C_;
    float *pot_, *fin_, *g_, *la_, *lb_;
    cudaGetSymbolAddress((void**)&C_,   d_C);
    cudaGetSymbolAddress((void**)&pot_, d_pot);
    cudaGetSymbolAddress((void**)&fin_, d_fin);
    cudaGetSymbolAddress((void**)&g_,   d_g);
    cudaGetSymbolAddress((void**)&la_,  d_la);
    cudaGetSymbolAddress((void**)&lb_,  d_lb);

    unsigned short* Cxx = C_ + 0 * CMAT;
    unsigned short* Cyy = C_ + 1 * CMAT;
    unsigned short* Cxy = C_ + 2 * CMAT;
    unsigned short* Cyx = C_ + 3 * CMAT;
    auto POT = [&](int buf, int j) { return pot_ + ((size_t)buf * 4 + j) * BN; };
    auto G   = [&](int bank, int j) { return g_ + ((size_t)bank * 4 + j) * BN; };

    logw_kernel<<<(BN + 255) / 256, 256>>>(alpha, beta, la_, lb_);

    cost_all<<<dim3(NPTS / 32, NPTS / 32, 24), dim3(32, 8)>>>(x, y, Cxx, Cyy, Cxy, Cyx);

    const double eps_list[8] = {
        4.0, 3.9999999999999996, 1.0, 0.25, 0.0625, 0.015625, 0.00390625, 0.0025
    };

    const unsigned short* CJ[4] = {Cxx, Cyy, Cyx, Cxy};
    const int GOUTI[4] = {0, 1, 3, 2};
    const float* LW[4] = {la_, lb_, lb_, la_};

    const int gx = BN / (8 * RPW);      // 1024 blocks per job
    dim3 smg(gx, 4);
    const double P23 = 8388608.0;       // 2^23

    // ---- init (eps = 4) ----
    {
        double eps = 4.0, eps_next = eps_list[0];
        double dqs = DQ * LOG2E / eps;
        SmJobs J;
        for (int j = 0; j < 4; j++) {
            J.C[j] = CJ[j];
            J.gin[j] = (j == 0 || j == 2) ? la_ : lb_;
            J.potold[j] = nullptr;
            J.out[j] = POT(0, j);
            J.gout[j] = G(0, GOUTI[j]);
            J.lw[j] = LW[j];
        }
        softmin_fused<true><<<smg, 256>>>(J, (float)dqs, (float)(P23 * dqs),
                                          (float)(-eps * LN2),
                                          (float)(LOG2E / eps_next), 0);
    }

    // ---- annealed loop ----
    int cur = 0, gb = 0;
    for (int i = 0; i < 8; i++) {
        double eps = eps_list[i];
        double eps_next = (i < 7) ? eps_list[i + 1] : 0.0025;
        double dqs = DQ * LOG2E / eps;
        int nxt = cur ^ 1;
        SmJobs J;
        for (int j = 0; j < 4; j++) {
            J.C[j] = CJ[j];
            J.gin[j] = G(gb, j);
            J.potold[j] = POT(cur, j);
            J.out[j] = POT(nxt, j);
            J.gout[j] = G(gb ^ 1, GOUTI[j]);
            J.lw[j] = LW[j];
        }
        softmin_fused<true><<<smg, 256>>>(J, (float)dqs, (float)(P23 * dqs),
                                          (float)(-eps * LN2),
                                          (float)(LOG2E / eps_next), 1);
        cur = nxt;
        gb ^= 1;
    }

    // ---- final extrapolation (fp32 exp path), SEQUENTIAL: b_x uses fresh a_y ----
    {
        double eps = 0.0025;
        double dqs = DQ * LOG2E / eps;
        float nel = (float)(-eps * LN2);
        float ien = (float)(LOG2E / eps);
        SmJobs J;
        for (int j = 0; j < 3; j++) {
            J.C[j] = CJ[j];
            J.gin[j] = G(gb, j);
            J.potold[j] = nullptr;
            J.out[j] = fin_ + (size_t)j * BN;
            J.gout[j] = (j == 2) ? G(gb ^ 1, 3) : nullptr;
            J.lw[j] = LW[j];
        }
        J.C[3] = CJ[3]; J.gin[3] = G(gb, 3); J.potold[3] = nullptr;
        J.out[3] = fin_ + 3 * (size_t)BN; J.gout[3] = nullptr; J.lw[3] = LW[3];
        softmin_fused<false><<<dim3(gx, 3), 256>>>(J, (float)dqs, (float)(P23 * dqs),
                                                   nel, ien, 0);

        SmJobs J2;
        for (int j = 0; j < 4; j++) {
            J2.C[j] = Cxy; J2.gin[j] = G(gb ^ 1, 3); J2.potold[j] = nullptr;
            J2.out[j] = fin_ + 3 * (size_t)BN; J2.gout[j] = nullptr; J2.lw[j] = lb_;
        }
        softmin_fused<false><<<dim3(gx, 1), 256>>>(J2, (float)dqs, (float)(P23 * dqs),
                                                   nel, ien, 0);
    }

    loss_kernel<<<B, 256>>>(alpha, beta, out);
}

// round 15
// speedup vs baseline: 1.5102x; 1.0600x over previous
#include <cuda_runtime.h>
#include <cuda_fp16.h>
#include <math.h>

#define B    8
#define NPTS 2048
#define BN   (B * NPTS)
#define CMAT ((size_t)B * NPTS * NPTS)

#define CMAX  1.5707964f
#define QSCL  (65535.0f / CMAX)
#define DQ    (1.5707964 / 65535.0)
#define LOG2E 1.4426950408889634
#define LN2   0.6931471805599453

#define RPW   2            // rows per warp -> 16 rows per 256-thread block

// ---------------- scratch (allocation-free: __device__ globals) ----------------
__device__ unsigned short d_C[4][B * NPTS * NPTS];   // Cxx, Cyy, Cxy, Cyx
__device__ float d_pot[2][4][BN];
__device__ float d_fin[4][BN];
__device__ float d_g[2][4][BN];                      // double-buffered weights
__device__ float d_la[BN];                           // log2e * log(alpha)
__device__ float d_lb[BN];

// ---------------- helpers ----------------
__device__ __forceinline__ unsigned int qcost(float t) {
    t = fminf(fmaxf(t, -1.0f + 1e-6f), 1.0f - 1e-6f);
    float ax = fabsf(t);
    float u  = 1.0f - ax;
    float s  = u * __frsqrt_rn(u);
    float p  = -0.0012624911f;
    p = fmaf(p, ax, 0.0066700901f);
    p = fmaf(p, ax, -0.0170881256f);
    p = fmaf(p, ax, 0.0308918810f);
    p = fmaf(p, ax, -0.0501743046f);
    p = fmaf(p, ax, 0.0889789874f);
    p = fmaf(p, ax, -0.2145988016f);
    p = fmaf(p, ax, 1.5707963050f);
    float r = s * p;
    float c = (t < 0.0f) ? (3.14159265359f - r) : r;
    return __float2uint_rn(c * 0.5f * QSCL);
}

// ---------------- kernels ----------------
__global__ void logw_kernel(const float* __restrict__ a, const float* __restrict__ bt,
                            float* __restrict__ la, float* __restrict__ lb) {
    int i = blockIdx.x * blockDim.x + threadIdx.x;
    if (i < BN) {
        float av = a[i];
        la[i] = (float)LOG2E * ((av > 0.f) ? logf(fmaxf(av, 1e-30f)) : -1e5f);
        float bv = bt[i];
        lb[i] = (float)LOG2E * ((bv > 0.f) ? logf(fmaxf(bv, 1e-30f)) : -1e5f);
    }
}

__global__ void cost_all(const float* __restrict__ x, const float* __restrict__ y,
                         unsigned short* __restrict__ Cxx, unsigned short* __restrict__ Cyy,
                         unsigned short* __restrict__ Cxy, unsigned short* __restrict__ Cyx) {
    int job = blockIdx.z >> 3;
    int b   = blockIdx.z & 7;
    const float *P, *Q;
    unsigned short *Co, *Ct;
    int tri;
    if (job == 0)      { P = x; Q = x; Co = Cxx; Ct = Cxx; tri = 1; }
    else if (job == 1) { P = y; Q = y; Co = Cyy; Ct = Cyy; tri = 1; }
    else               { P = x; Q = y; Co = Cxy; Ct = Cyx; tri = 0; }
    if (tri && (int)blockIdx.x < (int)blockIdx.y) return;

    __shared__ float xs[32][3], ys[32][3];
    __shared__ unsigned short t[32][33];
    int n0 = blockIdx.y * 32, m0 = blockIdx.x * 32;
    int tx = threadIdx.x, ty = threadIdx.y;
    int lt = ty * 32 + tx;
    if (lt < 96) {
        xs[lt / 3][lt % 3] = P[((size_t)b * NPTS + n0) * 3 + lt];
        ys[lt / 3][lt % 3] = Q[((size_t)b * NPTS + m0) * 3 + lt];
    }
    __syncthreads();
#pragma unroll
    for (int k = 0; k < 4; k++) {
        int nl = ty + 8 * k;
        float dot = xs[nl][0] * ys[tx][0] + xs[nl][1] * ys[tx][1] + xs[nl][2] * ys[tx][2];
        unsigned int q = qcost(dot);
        t[nl][tx] = (unsigned short)q;
        Co[((size_t)b * NPTS + n0 + nl) * NPTS + m0 + tx] = (unsigned short)q;
    }
    __syncthreads();
#pragma unroll
    for (int k = 0; k < 4; k++) {
        int ml = ty + 8 * k;
        Ct[((size_t)b * NPTS + m0 + ml) * NPTS + n0 + tx] = t[tx][ml];
    }
}

// ---- softmin v8: PRMT unpack; template NOMAX = fixed-shift path (eps >= 0.25):
// shift G = max_batch(g) folded into staged weights at staging time -> no
// per-chunk max, no shift subs, warp merge is a plain shuffle-add.
struct SmJobs {
    const unsigned short* C[4];
    const float*          gin[4];
    const float*          potold[4];
    float*                out[4];
    float*                gout[4];
    const float*          lw[4];
};

template <bool NOMAX>
__global__ void __launch_bounds__(256, 5) softmin_fused(
        SmJobs J, float dqs, float goff, float negeln2, float ienl2, int blend) {
    __shared__ float4 sgA[256];      // staged elems 8i..8i+3
    __shared__ float4 sgB[256];      // staged elems 8i+4..8i+7
    __shared__ float  smax[8];

    int tid  = threadIdx.x;
    int warp = tid >> 5, lane = tid & 31;
    int job  = blockIdx.y;
    int rbase = blockIdx.x * (8 * RPW) + warp * RPW;
    int b     = rbase >> 11;

    const unsigned short* Cb = J.C[job];

    const uint4* cp0 = (const uint4*)(Cb + (size_t)rbase * NPTS);
    uint4 q = __ldcs(cp0 + lane);

    // Stage weights. NOMAX: also compute batch max G and fold -G into the stage.
    float G = 0.f;
    {
        const float4* gp4 = (const float4*)(J.gin[job] + b * NPTS);
        float4 gv0 = gp4[tid];
        float4 gv1 = gp4[tid + 256];
        if (NOMAX) {
            float lm = fmaxf(fmaxf(fmaxf(gv0.x, gv0.y), fmaxf(gv0.z, gv0.w)),
                             fmaxf(fmaxf(gv1.x, gv1.y), fmaxf(gv1.z, gv1.w)));
#pragma unroll
            for (int o = 16; o; o >>= 1)
                lm = fmaxf(lm, __shfl_xor_sync(0xffffffffu, lm, o));
            if (lane == 0) smax[warp] = lm;
            __syncthreads();
            G = smax[0];
#pragma unroll
            for (int i = 1; i < 8; i++) G = fmaxf(G, smax[i]);
        }
        float off = goff - G;
        gv0.x += off; gv0.y += off; gv0.z += off; gv0.w += off;
        gv1.x += off; gv1.y += off; gv1.z += off; gv1.w += off;
        if (tid & 1) sgB[tid >> 1] = gv0; else sgA[tid >> 1] = gv0;
        int t2 = tid + 256;
        if (t2 & 1) sgB[t2 >> 1] = gv1; else sgA[t2 >> 1] = gv1;
    }
    __syncthreads();

#pragma unroll
    for (int k = 0; k < RPW; k++) {
        int row = rbase + k;
        float m = 0.f, s = 0.f;
#pragma unroll
        for (int t = 0; t < 8; t++) {
            uint4 qn;
            if (t < 7) {
                qn = __ldcs((const uint4*)(Cb + (size_t)row * NPTS) + (t + 1) * 32 + lane);
            } else if (k < RPW - 1) {
                qn = __ldcs((const uint4*)(Cb + (size_t)(row + 1) * NPTS) + lane);
            }
            int gi = t * 32 + lane;
            float4 gA = sgA[gi];
            float4 gB = sgB[gi];
            float f0 = __uint_as_float(__byte_perm(q.x, 0x4B000000u, 0x7410));
            float f1 = __uint_as_float(__byte_perm(q.x, 0x4B000000u, 0x7432));
            float f2 = __uint_as_float(__byte_perm(q.y, 0x4B000000u, 0x7410));
            float f3 = __uint_as_float(__byte_perm(q.y, 0x4B000000u, 0x7432));
            float f4 = __uint_as_float(__byte_perm(q.z, 0x4B000000u, 0x7410));
            float f5 = __uint_as_float(__byte_perm(q.z, 0x4B000000u, 0x7432));
            float f6 = __uint_as_float(__byte_perm(q.w, 0x4B000000u, 0x7410));
            float f7 = __uint_as_float(__byte_perm(q.w, 0x4B000000u, 0x7432));
            float v0 = fmaf(f0, -dqs, gA.x);
            float v1 = fmaf(f1, -dqs, gA.y);
            float v2 = fmaf(f2, -dqs, gA.z);
            float v3 = fmaf(f3, -dqs, gA.w);
            float v4 = fmaf(f4, -dqs, gB.x);
            float v5 = fmaf(f5, -dqs, gB.y);
            float v6 = fmaf(f6, -dqs, gB.z);
            float v7 = fmaf(f7, -dqs, gB.w);
            if (NOMAX) {
                // exponents already shifted by G (all <= 0): direct f16x2 exp + sum
                __half2 h0 = h2exp2(__floats2half2_rn(v0, v1));
                __half2 h1 = h2exp2(__floats2half2_rn(v2, v3));
                h0 = __hadd2(h0, h2exp2(__floats2half2_rn(v4, v5)));
                h1 = __hadd2(h1, h2exp2(__floats2half2_rn(v6, v7)));
                h0 = __hadd2(h0, h1);
                float2 f = __half22float2(h0);
                s += f.x + f.y;
            } else {
                float mc = fmaxf(fmaxf(fmaxf(v0, v1), fmaxf(v2, v3)),
                                 fmaxf(fmaxf(v4, v5), fmaxf(v6, v7)));
                __half2 h0 = h2exp2(__floats2half2_rn(v0 - mc, v1 - mc));
                __half2 h1 = h2exp2(__floats2half2_rn(v2 - mc, v3 - mc));
                h0 = __hadd2(h0, h2exp2(__floats2half2_rn(v4 - mc, v5 - mc)));
                h1 = __hadd2(h1, h2exp2(__floats2half2_rn(v6 - mc, v7 - mc)));
                h0 = __hadd2(h0, h1);
                float2 f = __half22float2(h0);
                float sc = f.x + f.y;
                if (t == 0) {
                    m = mc; s = sc;
                } else {
                    float M = fmaxf(m, mc);
                    s = s * exp2f(m - M) + sc * exp2f(mc - M);
                    m = M;
                }
            }
            q = qn;
        }
        if (NOMAX) {
#pragma unroll
            for (int o = 16; o; o >>= 1)
                s += __shfl_xor_sync(0xffffffffu, s, o);
            m = G;
        } else {
#pragma unroll
            for (int o = 16; o; o >>= 1) {
                float mo = __shfl_xor_sync(0xffffffffu, m, o);
                float so = __shfl_xor_sync(0xffffffffu, s, o);
                float M  = fmaxf(m, mo);
                s = s * exp2f(m - M) + so * exp2f(mo - M);
                m = M;
            }
        }
        if (lane == 0) {
            float r = negeln2 * (m + log2f(s));
            if (blend) r = 0.5f * (J.potold[job][row] + r);
            J.out[job][row] = r;
            if (J.gout[job])
                J.gout[job][row] = fmaf(r, ienl2, J.lw[job][row]);
        }
    }
}

__global__ void loss_kernel(const float* __restrict__ alpha, const float* __restrict__ beta,
                            float* __restrict__ out) {
    __shared__ double red[8];
    int b = blockIdx.x, tid = threadIdx.x;
    double acc = 0.0;
    for (int i = tid; i < NPTS; i += 256) {
        int idx = b * NPTS + i;
        acc += (double)alpha[idx] * ((double)d_fin[3][idx] - (double)d_fin[0][idx]);
        acc += (double)beta[idx]  * ((double)d_fin[2][idx] - (double)d_fin[1][idx]);
    }
#pragma unroll
    for (int o = 16; o; o >>= 1)
        acc += __shfl_xor_sync(0xffffffffu, acc, o);
    if ((tid & 31) == 0) red[tid >> 5] = acc;
    __syncthreads();
    if (tid == 0) {
        double tot = red[0];
#pragma unroll
        for (int i = 1; i < 8; i++) tot += red[i];
        out[b] = (float)tot;
    }
}

// ---------------- host orchestration ----------------
extern "C" void kernel_launch(void* const* d_in, const int* in_sizes, int n_in,
                              void* d_out, int out_size) {
    const float* alpha = (const float*)d_in[0];
    const float* x     = (const float*)d_in[1];
    const float* beta  = (const float*)d_in[2];
    const float* y     = (const float*)d_in[3];
    float* out = (float*)d_out;

    unsigned short* C_;
    float *pot_, *fin_, *g_, *la_, *lb_;
    cudaGetSymbolAddress((void**)&C_,   d_C);
    cudaGetSymbolAddress((void**)&pot_, d_pot);
    cudaGetSymbolAddress((void**)&fin_, d_fin);
    cudaGetSymbolAddress((void**)&g_,   d_g);
    cudaGetSymbolAddress((void**)&la_,  d_la);
    cudaGetSymbolAddress((void**)&lb_,  d_lb);

    unsigned short* Cxx = C_ + 0 * CMAT;
    unsigned short* Cyy = C_ + 1 * CMAT;
    unsigned short* Cxy = C_ + 2 * CMAT;
    unsigned short* Cyx = C_ + 3 * CMAT;
    auto POT = [&](int buf, int j) { return pot_ + ((size_t)buf * 4 + j) * BN; };
    auto G   = [&](int bank, int j) { return g_ + ((size_t)bank * 4 + j) * BN; };

    logw_kernel<<<(BN + 255) / 256, 256>>>(alpha, beta, la_, lb_);

    cost_all<<<dim3(NPTS / 32, NPTS / 32, 24), dim3(32, 8)>>>(x, y, Cxx, Cyy, Cxy, Cyx);

    const double eps_list[8] = {
        4.0, 3.9999999999999996, 1.0, 0.25, 0.0625, 0.015625, 0.00390625, 0.0025
    };

    const unsigned short* CJ[4] = {Cxx, Cyy, Cyx, Cxy};
    const int GOUTI[4] = {0, 1, 3, 2};
    const float* LW[4] = {la_, lb_, lb_, la_};

    const int gx = BN / (8 * RPW);      // 1024 blocks per job
    dim3 smg(gx, 4);
    const double P23 = 8388608.0;       // 2^23

    // ---- init (eps = 4): fixed-shift path ----
    {
        double eps = 4.0, eps_next = eps_list[0];
        double dqs = DQ * LOG2E / eps;
        SmJobs J;
        for (int j = 0; j < 4; j++) {
            J.C[j] = CJ[j];
            J.gin[j] = (j == 0 || j == 2) ? la_ : lb_;
            J.potold[j] = nullptr;
            J.out[j] = POT(0, j);
            J.gout[j] = G(0, GOUTI[j]);
            J.lw[j] = LW[j];
        }
        softmin_fused<true><<<smg, 256>>>(J, (float)dqs, (float)(P23 * dqs),
                                          (float)(-eps * LN2),
                                          (float)(LOG2E / eps_next), 0);
    }

    // ---- annealed loop: fixed-shift for eps >= 0.25 (i < 4), online-max after ----
    int cur = 0, gb = 0;
    for (int i = 0; i < 8; i++) {
        double eps = eps_list[i];
        double eps_next = (i < 7) ? eps_list[i + 1] : 0.0025;
        double dqs = DQ * LOG2E / eps;
        int nxt = cur ^ 1;
        SmJobs J;
        for (int j = 0; j < 4; j++) {
            J.C[j] = CJ[j];
            J.gin[j] = G(gb, j);
            J.potold[j] = POT(cur, j);
            J.out[j] = POT(nxt, j);
            J.gout[j] = G(gb ^ 1, GOUTI[j]);
            J.lw[j] = LW[j];
        }
        if (i < 4)
            softmin_fused<true><<<smg, 256>>>(J, (float)dqs, (float)(P23 * dqs),
                                              (float)(-eps * LN2),
                                              (float)(LOG2E / eps_next), 1);
        else
            softmin_fused<false><<<smg, 256>>>(J, (float)dqs, (float)(P23 * dqs),
                                               (float)(-eps * LN2),
                                               (float)(LOG2E / eps_next), 1);
        cur = nxt;
        gb ^= 1;
    }

    // ---- final extrapolation (eps = 0.0025), online-max + f16 exp;
    //      SEQUENTIAL: b_x uses fresh a_y ----
    {
        double eps = 0.0025;
        double dqs = DQ * LOG2E / eps;
        float nel = (float)(-eps * LN2);
        float ien = (float)(LOG2E / eps);
        SmJobs J;
        for (int j = 0; j < 3; j++) {
            J.C[j] = CJ[j];
            J.gin[j] = G(gb, j);
            J.potold[j] = nullptr;
            J.out[j] = fin_ + (size_t)j * BN;
            J.gout[j] = (j == 2) ? G(gb ^ 1, 3) : nullptr;
            J.lw[j] = LW[j];
        }
        J.C[3] = CJ[3]; J.gin[3] = G(gb, 3); J.potold[3] = nullptr;
        J.out[3] = fin_ + 3 * (size_t)BN; J.gout[3] = nullptr; J.lw[3] = LW[3];
        softmin_fused<false><<<dim3(gx, 3), 256>>>(J, (float)dqs, (float)(P23 * dqs),
                                                   nel, ien, 0);

        SmJobs J2;
        for (int j = 0; j < 4; j++) {
            J2.C[j] = Cxy; J2.gin[j] = G(gb ^ 1, 3); J2.potold[j] = nullptr;
            J2.out[j] = fin_ + 3 * (size_t)BN; J2.gout[j] = nullptr; J2.lw[j] = lb_;
        }
        softmin_fused<false><<<dim3(gx, 1), 256>>>(J2, (float)dqs, (float)(P23 * dqs),
                                                   nel, ien, 0);
    }

    loss_kernel<<<B, 256>>>(alpha, beta, out);
}